// round 7
// baseline (speedup 1.0000x reference)
#include <cuda_runtime.h>
#include <cuda_bf16.h>
#include <cuda_fp16.h>

#define HH   1024
#define WW   1024
#define RAD  40
#define EPSF 1e-3f
#define MAXIMG 12
#define HWSZ (HH * WW)

#define BAND  86
#define NBAND 12         // ceil(1024 / 86)

#define PADL 40          // left padding (zeros) in csp
#define CSPN 1112        // PADL + 1024 + 48 right padding

// ---------------------------------------------------------------------------
// Scratch: only (a,b) crosses between the two kernels, as half2 (4B/px).
// Inputs centered at 0 before accumulation, so fp16 storage of (a,b) is the
// only rounding source; vertical/horizontal sums now live in fp32 registers.
// ---------------------------------------------------------------------------
__device__ unsigned g_abh[MAXIMG * HWSZ];

static __device__ __forceinline__ unsigned pack2(float a, float b)
{
    __half2 h = __floats2half2_rn(a, b);
    return *reinterpret_cast<unsigned*>(&h);
}
static __device__ __forceinline__ float2 unpack2(unsigned u)
{
    return __half22float2(*reinterpret_cast<__half2*>(&u));
}

// ---------------------------------------------------------------------------
// Stage 1 (fused V+H): block owns a band of rows x full width.
// Vertical sliding sums of (I',p',I'p',I'I') in registers; per row a
// block-wide prefix scan completes the 2D box; fused a/b -> g_abh.
// grid = (NBAND, nimg), block = 256
// ---------------------------------------------------------------------------
__global__ __launch_bounds__(256)
void stage1(const float* __restrict__ I, const float* __restrict__ P)
{
    __shared__ float csp[4][CSPN];
    __shared__ float wsum[4][8];

    int t    = threadIdx.x;
    int lane = t & 31;
    int warp = t >> 5;
    int y0   = blockIdx.x * BAND;
    int y1   = min(y0 + BAND, HH);
    size_t base = (size_t)blockIdx.y * HWSZ + (size_t)t * 4;

    const float* __restrict__ Ib = I + base;
    const float* __restrict__ Pb = P + base;
    unsigned*    __restrict__ Ab = g_abh + base;

    // --- prime vertical sums over [y0-RAD, y0+RAD] (clamped) ---
    float4 sI  = make_float4(0.f, 0.f, 0.f, 0.f);
    float4 sP  = sI, sIP = sI, sII = sI;
    {
        int ys = max(y0 - RAD, 0);
        int ye = min(y0 + RAD, HH - 1);
#pragma unroll 4
        for (int y = ys; y <= ye; y++) {
            float4 vi = *(const float4*)(Ib + (size_t)y * WW);
            float4 vp = *(const float4*)(Pb + (size_t)y * WW);
            vi.x -= 0.5f; vi.y -= 0.5f; vi.z -= 0.5f; vi.w -= 0.5f;
            vp.x -= 0.5f; vp.y -= 0.5f; vp.z -= 0.5f; vp.w -= 0.5f;
            sI.x  += vi.x;        sI.y  += vi.y;        sI.z  += vi.z;        sI.w  += vi.w;
            sP.x  += vp.x;        sP.y  += vp.y;        sP.z  += vp.z;        sP.w  += vp.w;
            sIP.x += vi.x * vp.x; sIP.y += vi.y * vp.y; sIP.z += vi.z * vp.z; sIP.w += vi.w * vp.w;
            sII.x += vi.x * vi.x; sII.y += vi.y * vi.y; sII.z += vi.z * vi.z; sII.w += vi.w * vi.w;
        }
    }

    int x = t * 4;

    for (int y = y0; y < y1; y++) {
        // --- prefetch add/sub rows (independent of the scan below) ---
        int ya = y + RAD + 1;
        int yu = y - RAD;
        float4 aI = make_float4(0.f, 0.f, 0.f, 0.f), aP = aI, uI = aI, uP = aI;
        if (ya < HH) {
            aI = *(const float4*)(Ib + (size_t)ya * WW);
            aP = *(const float4*)(Pb + (size_t)ya * WW);
            aI.x -= 0.5f; aI.y -= 0.5f; aI.z -= 0.5f; aI.w -= 0.5f;
            aP.x -= 0.5f; aP.y -= 0.5f; aP.z -= 0.5f; aP.w -= 0.5f;
        }
        if (yu >= 0) {
            uI = *(const float4*)(Ib + (size_t)yu * WW);
            uP = *(const float4*)(Pb + (size_t)yu * WW);
            uI.x -= 0.5f; uI.y -= 0.5f; uI.z -= 0.5f; uI.w -= 0.5f;
            uP.x -= 0.5f; uP.y -= 0.5f; uP.z -= 0.5f; uP.w -= 0.5f;
        }

        // --- block-wide prefix scan of the 4 vertical sums ---
        float e[4][4] = {
            { sI.x,  sI.y,  sI.z,  sI.w  },
            { sP.x,  sP.y,  sP.z,  sP.w  },
            { sIP.x, sIP.y, sIP.z, sIP.w },
            { sII.x, sII.y, sII.z, sII.w }
        };

        float loc[4][4], v[4];
#pragma unroll
        for (int q = 0; q < 4; q++) {
            loc[q][0] = e[q][0];
            loc[q][1] = loc[q][0] + e[q][1];
            loc[q][2] = loc[q][1] + e[q][2];
            loc[q][3] = loc[q][2] + e[q][3];
            v[q] = loc[q][3];
        }
#pragma unroll
        for (int d = 1; d < 32; d <<= 1) {
#pragma unroll
            for (int q = 0; q < 4; q++) {
                float n = __shfl_up_sync(0xffffffffu, v[q], d);
                if (lane >= d) v[q] += n;
            }
        }
        if (lane == 31) {
#pragma unroll
            for (int q = 0; q < 4; q++) wsum[q][warp] = v[q];
        }
        __syncthreads();

#pragma unroll
        for (int q = 0; q < 4; q++) {
            float wb = 0.f;
#pragma unroll
            for (int w2 = 0; w2 < 7; w2++)
                wb += (w2 < warp) ? wsum[q][w2] : 0.f;
            float excl = wb + v[q] - loc[q][3];
            *(float4*)&csp[q][PADL + x] =
                make_float4(excl, excl + loc[q][0], excl + loc[q][1], excl + loc[q][2]);
            if (t < 10)
                *(float4*)&csp[q][t * 4] = make_float4(0.f, 0.f, 0.f, 0.f);
            if (t >= 240 && t < 252) {
                float tot = wsum[q][0] + wsum[q][1] + wsum[q][2] + wsum[q][3]
                          + wsum[q][4] + wsum[q][5] + wsum[q][6] + wsum[q][7];
                *(float4*)&csp[q][PADL + WW + (t - 240) * 4] =
                    make_float4(tot, tot, tot, tot);
            }
        }
        __syncthreads();

        float B[4][4];
#pragma unroll
        for (int q = 0; q < 4; q++) {
            float4 L  = *(const float4*)&csp[q][PADL + x - RAD];
            float4 HA = *(const float4*)&csp[q][PADL + x + RAD];
            float4 HB = *(const float4*)&csp[q][PADL + x + RAD + 4];
            B[q][0] = HA.y - L.x;
            B[q][1] = HA.z - L.y;
            B[q][2] = HA.w - L.z;
            B[q][3] = HB.x - L.w;
        }

        float cy = (float)(min(y + RAD, HH - 1) - max(y - RAD, 0) + 1);

        uint4 outv;
        unsigned* ov = &outv.x;
#pragma unroll
        for (int k = 0; k < 4; k++) {
            float cx  = (float)(min(x + k + RAD, WW - 1) - max(x + k - RAD, 0) + 1);
            float inv = 1.0f / (cx * cy);
            float mIc = B[0][k] * inv;
            float mPc = B[1][k] * inv;
            float cov = B[2][k] * inv - mIc * mPc;
            float var = B[3][k] * inv - mIc * mIc;
            float a   = cov / (var + EPSF);
            float b   = (mPc + 0.5f) - a * (mIc + 0.5f);
            ov[k] = pack2(a, b);
        }
        *(uint4*)(Ab + (size_t)y * WW) = outv;

        // --- slide vertical window ---
        sI.x  += aI.x - uI.x;         sI.y  += aI.y - uI.y;
        sI.z  += aI.z - uI.z;         sI.w  += aI.w - uI.w;
        sP.x  += aP.x - uP.x;         sP.y  += aP.y - uP.y;
        sP.z  += aP.z - uP.z;         sP.w  += aP.w - uP.w;
        sIP.x += aI.x * aP.x - uI.x * uP.x;  sIP.y += aI.y * aP.y - uI.y * uP.y;
        sIP.z += aI.z * aP.z - uI.z * uP.z;  sIP.w += aI.w * aP.w - uI.w * uP.w;
        sII.x += aI.x * aI.x - uI.x * uI.x;  sII.y += aI.y * aI.y - uI.y * uI.y;
        sII.z += aI.z * aI.z - uI.z * uI.z;  sII.w += aI.w * aI.w - uI.w * uI.w;
    }
}

// ---------------------------------------------------------------------------
// Stage 2 (fused V+H): vertical sliding sums of (a,b) in registers; per-row
// scan completes the box; out = mean_a * I + mean_b.
// grid = (NBAND, nimg), block = 256
// ---------------------------------------------------------------------------
__global__ __launch_bounds__(256)
void stage2(const float* __restrict__ I, float* __restrict__ out)
{
    __shared__ float csp[2][CSPN];
    __shared__ float wsum[2][8];

    int t    = threadIdx.x;
    int lane = t & 31;
    int warp = t >> 5;
    int y0   = blockIdx.x * BAND;
    int y1   = min(y0 + BAND, HH);
    size_t base = (size_t)blockIdx.y * HWSZ + (size_t)t * 4;

    const unsigned* __restrict__ Ab = g_abh + base;
    const float*    __restrict__ Ib = I + base;
    float*          __restrict__ Ob = out + base;

    float4 sa = make_float4(0.f, 0.f, 0.f, 0.f);
    float4 sb = sa;
    {
        int ys = max(y0 - RAD, 0);
        int ye = min(y0 + RAD, HH - 1);
#pragma unroll 4
        for (int y = ys; y <= ye; y++) {
            uint4 r = *(const uint4*)(Ab + (size_t)y * WW);
            float2 c0 = unpack2(r.x), c1 = unpack2(r.y);
            float2 c2 = unpack2(r.z), c3 = unpack2(r.w);
            sa.x += c0.x; sa.y += c1.x; sa.z += c2.x; sa.w += c3.x;
            sb.x += c0.y; sb.y += c1.y; sb.z += c2.y; sb.w += c3.y;
        }
    }

    int x = t * 4;

    for (int y = y0; y < y1; y++) {
        int ya = y + RAD + 1;
        int yu = y - RAD;
        uint4 addr = make_uint4(0u, 0u, 0u, 0u);
        uint4 subr = addr;
        if (ya < HH) addr = *(const uint4*)(Ab + (size_t)ya * WW);
        if (yu >= 0) subr = *(const uint4*)(Ab + (size_t)yu * WW);
        float4 vI = *(const float4*)(Ib + (size_t)y * WW);

        float e[2][4] = {
            { sa.x, sa.y, sa.z, sa.w },
            { sb.x, sb.y, sb.z, sb.w }
        };

        float loc[2][4], v[2];
#pragma unroll
        for (int q = 0; q < 2; q++) {
            loc[q][0] = e[q][0];
            loc[q][1] = loc[q][0] + e[q][1];
            loc[q][2] = loc[q][1] + e[q][2];
            loc[q][3] = loc[q][2] + e[q][3];
            v[q] = loc[q][3];
        }
#pragma unroll
        for (int d = 1; d < 32; d <<= 1) {
#pragma unroll
            for (int q = 0; q < 2; q++) {
                float n = __shfl_up_sync(0xffffffffu, v[q], d);
                if (lane >= d) v[q] += n;
            }
        }
        if (lane == 31) {
#pragma unroll
            for (int q = 0; q < 2; q++) wsum[q][warp] = v[q];
        }
        __syncthreads();

#pragma unroll
        for (int q = 0; q < 2; q++) {
            float wb = 0.f;
#pragma unroll
            for (int w2 = 0; w2 < 7; w2++)
                wb += (w2 < warp) ? wsum[q][w2] : 0.f;
            float excl = wb + v[q] - loc[q][3];
            *(float4*)&csp[q][PADL + x] =
                make_float4(excl, excl + loc[q][0], excl + loc[q][1], excl + loc[q][2]);
            if (t < 10)
                *(float4*)&csp[q][t * 4] = make_float4(0.f, 0.f, 0.f, 0.f);
            if (t >= 240 && t < 252) {
                float tot = wsum[q][0] + wsum[q][1] + wsum[q][2] + wsum[q][3]
                          + wsum[q][4] + wsum[q][5] + wsum[q][6] + wsum[q][7];
                *(float4*)&csp[q][PADL + WW + (t - 240) * 4] =
                    make_float4(tot, tot, tot, tot);
            }
        }
        __syncthreads();

        float B[2][4];
#pragma unroll
        for (int q = 0; q < 2; q++) {
            float4 L  = *(const float4*)&csp[q][PADL + x - RAD];
            float4 HA = *(const float4*)&csp[q][PADL + x + RAD];
            float4 HB = *(const float4*)&csp[q][PADL + x + RAD + 4];
            B[q][0] = HA.y - L.x;
            B[q][1] = HA.z - L.y;
            B[q][2] = HA.w - L.z;
            B[q][3] = HB.x - L.w;
        }

        float cy = (float)(min(y + RAD, HH - 1) - max(y - RAD, 0) + 1);
        float iv[4] = { vI.x, vI.y, vI.z, vI.w };

        float4 o;
        float* op = &o.x;
#pragma unroll
        for (int k = 0; k < 4; k++) {
            float cx  = (float)(min(x + k + RAD, WW - 1) - max(x + k - RAD, 0) + 1);
            float inv = 1.0f / (cx * cy);
            op[k] = (B[0][k] * inv) * iv[k] + (B[1][k] * inv);
        }
        *(float4*)(Ob + (size_t)y * WW) = o;

        // slide vertical window
        float2 a0 = unpack2(addr.x), a1 = unpack2(addr.y);
        float2 a2 = unpack2(addr.z), a3 = unpack2(addr.w);
        float2 u0 = unpack2(subr.x), u1 = unpack2(subr.y);
        float2 u2 = unpack2(subr.z), u3 = unpack2(subr.w);
        sa.x += a0.x - u0.x; sa.y += a1.x - u1.x;
        sa.z += a2.x - u2.x; sa.w += a3.x - u3.x;
        sb.x += a0.y - u0.y; sb.y += a1.y - u1.y;
        sb.z += a2.y - u2.y; sb.w += a3.y - u3.y;
    }
}

// ---------------------------------------------------------------------------
extern "C" void kernel_launch(void* const* d_in, const int* in_sizes, int n_in,
                              void* d_out, int out_size)
{
    const float* I = (const float*)d_in[0];
    const float* P = (const float*)d_in[1];
    float* out     = (float*)d_out;

    int nimg = in_sizes[0] / HWSZ;      // B*C images of 1024x1024
    if (nimg > MAXIMG) nimg = MAXIMG;

    dim3 grid(NBAND, nimg);
    stage1<<<grid, 256>>>(I, P);
    stage2<<<grid, 256>>>(I, out);
}